// round 5
// baseline (speedup 1.0000x reference)
#include <cuda_runtime.h>
#include <math.h>

#define Bn 512
#define Jn 101
#define Mn 50
#define En 128
#define Dn 60
#define DP 64
#define WS 65
#define Pn 5120
#define TPB 1024
#define NW  (TPB/32)
#define GRID 148

// ---------------- device scratch ----------------
__device__ float g_Wft[En * En];   // Wft[k*128+e] = (R_w @ Bc_w)[e][k]
__device__ float g_bf[En];         // R_w @ Bc_b + R_b
__device__ float g_mask[Bn * Mn];  // 0 or -inf

__global__ void k_prep(const float* __restrict__ Bc_w, const float* __restrict__ Bc_b,
                       const float* __restrict__ R_w, const float* __restrict__ R_b)
{
    int e = blockIdx.x;
    int k = threadIdx.x;
    float acc = 0.f;
    for (int j = 0; j < En; j++)
        acc += R_w[e * En + j] * Bc_w[j * En + k];
    g_Wft[k * En + e] = acc;
    if (k == 0) {
        float s = R_b[e];
        for (int j = 0; j < En; j++) s += R_w[e * En + j] * Bc_b[j];
        g_bf[e] = s;
    }
}

__global__ void k_mask_init()
{
    int i = blockIdx.x * blockDim.x + threadIdx.x;
    if (i < Bn * Mn) g_mask[i] = 0.f;
}

__global__ void k_mask_scatter(const int* __restrict__ pad)
{
    int i = blockIdx.x * blockDim.x + threadIdx.x;
    if (i < Pn) {
        int b = pad[i];
        int m = pad[Pn + i];
        if (b >= 0 && b < Bn && m >= 0 && m < Mn)
            g_mask[b * Mn + m] = -INFINITY;
    }
}

// ---------------- smem layout (float offsets) ----------------
#define OFF_TV   0          // 101*128 = 12928 (overlaid by per-warp attn scratch in phase 3)
#define OFF_SU   12928      // 6400
#define OFF_TPN  19328      // 101*64 = 6464
#define OFF_CU   25792      // 6400
#define OFF_BFV  32192      // 128
#define OFF_ATW  32320      // 128*65 = 8320
#define OFF_ACW  40640      // 8320
#define OFF_CPT  48960      // 60*50 = 3000
#define OFF_ATB  51960      // 64
#define OFF_ACB  52024      // 64
#define OFF_MSK  52088      // 64
#define OFF_IDS  52152      // ints: cids 50 + jids 101
#define SMEM_FLOATS (OFF_IDS + 152)
#define SMEM_BYTES  (SMEM_FLOATS * 4)

__device__ __forceinline__ float wredsum(float v) {
    #pragma unroll
    for (int o = 16; o > 0; o >>= 1) v += __shfl_xor_sync(0xffffffffu, v, o);
    return v;
}
__device__ __forceinline__ float wredmax(float v) {
    #pragma unroll
    for (int o = 16; o > 0; o >>= 1) v = fmaxf(v, __shfl_xor_sync(0xffffffffu, v, o));
    return v;
}

__global__ __launch_bounds__(TPB, 1) void k_main(
    const int* __restrict__ titems, const int* __restrict__ citems,
    const float* __restrict__ t_emb, const float* __restrict__ c_emb,
    const float* __restrict__ Ac_w, const float* __restrict__ Ac_b,
    const float* __restrict__ At_w, const float* __restrict__ At_b,
    float* __restrict__ out)
{
    extern __shared__ float sm[];
    float* tv   = sm + OFF_TV;
    float* su   = sm + OFF_SU;
    float* tpn  = sm + OFF_TPN;
    float* cu   = sm + OFF_CU;
    float* bfv  = sm + OFF_BFV;
    float* atw  = sm + OFF_ATW;
    float* acw  = sm + OFF_ACW;
    float* cpt  = sm + OFF_CPT;
    float* atb  = sm + OFF_ATB;
    float* acb  = sm + OFF_ACB;
    float* mskf = sm + OFF_MSK;
    int*   cids = (int*)(sm + OFF_IDS);
    int*   jids = cids + Mn;

    const int tid = threadIdx.x;
    const int w   = tid >> 5, l = tid & 31;

    // ======== stage weights ONCE per CTA ========
    if (tid < DP) {
        atb[tid] = (tid < Dn) ? At_b[tid] : 0.f;
        acb[tid] = (tid < Dn) ? Ac_b[tid] : 0.f;
    }
    if (tid < En) bfv[tid] = g_bf[tid];
    for (int i = tid; i < Dn * En; i += TPB) {
        int d = i >> 7, k = i & 127;
        atw[k * WS + d] = At_w[i];
        acw[k * WS + d] = Ac_w[i];
    }
    for (int i = tid; i < En * 4; i += TPB) {
        int k = i >> 2, c = Dn + (i & 3);
        atw[k * WS + c] = 0.f;
        acw[k * WS + c] = 0.f;
    }

    // ======== persistent batch loop ========
    for (int b = blockIdx.x; b < Bn; b += GRID) {
        __syncthreads();   // weights ready / previous batch phase-3 done

        if (tid < Mn) { cids[tid] = citems[b * Mn + tid]; mskf[tid] = g_mask[b * Mn + tid]; }
        if (tid < Jn) jids[tid] = titems[b * Jn + tid];
        __syncthreads();

        // gather embeddings (float4)
        {
            const float4* cef = (const float4*)c_emb;
            const float4* tef = (const float4*)t_emb;
            float4* suf = (float4*)su;
            float4* tvf = (float4*)tv;
            for (int i = tid; i < Mn * 32; i += TPB)
                suf[i] = cef[(size_t)cids[i >> 5] * 32 + (i & 31)];
            for (int i = tid; i < Jn * 32; i += TPB)
                tvf[i] = tef[(size_t)jids[i >> 5] * 32 + (i & 31)];
        }
        __syncthreads();

        // ========== phase 2: 55 warp-passes (13 cp + 26 tp + 16 cu) ==========
        for (int p = w; p < 55; p += NW) {
            if (p < 39) {
                // projection pass: 4 rows x (d0=l, d1=l+32), normalized on store
                const bool iscp = (p < 13);
                const int base = iscp ? 4 * p : 4 * (p - 13);
                const int rmax = iscp ? (Mn - 1) : (Jn - 1);
                const float* src  = iscp ? su : tv;
                const float* wkd  = iscp ? acw : atw;
                const float* bias = iscp ? acb : atb;
                int r0 = min(base,     rmax), r1 = min(base + 1, rmax);
                int r2 = min(base + 2, rmax), r3 = min(base + 3, rmax);
                const float4* s0 = (const float4*)(src + r0 * En);
                const float4* s1 = (const float4*)(src + r1 * En);
                const float4* s2 = (const float4*)(src + r2 * En);
                const float4* s3 = (const float4*)(src + r3 * En);
                float bl0 = bias[l], bl1 = bias[l + 32];
                float a00 = bl0, a01 = bl1, a10 = bl0, a11 = bl1;
                float a20 = bl0, a21 = bl1, a30 = bl0, a31 = bl1;
                #pragma unroll 4
                for (int k4 = 0; k4 < 32; k4++) {
                    float4 v0 = s0[k4], v1 = s1[k4], v2 = s2[k4], v3 = s3[k4];
                    const float* wr = wkd + k4 * 4 * WS;
                    float w00 = wr[l],        w01 = wr[l + 32];
                    float w10 = wr[WS + l],   w11 = wr[WS + l + 32];
                    float w20 = wr[2*WS + l], w21 = wr[2*WS + l + 32];
                    float w30 = wr[3*WS + l], w31 = wr[3*WS + l + 32];
                    a00 += v0.x*w00 + v0.y*w10 + v0.z*w20 + v0.w*w30;
                    a01 += v0.x*w01 + v0.y*w11 + v0.z*w21 + v0.w*w31;
                    a10 += v1.x*w00 + v1.y*w10 + v1.z*w20 + v1.w*w30;
                    a11 += v1.x*w01 + v1.y*w11 + v1.z*w21 + v1.w*w31;
                    a20 += v2.x*w00 + v2.y*w10 + v2.z*w20 + v2.w*w30;
                    a21 += v2.x*w01 + v2.y*w11 + v2.z*w21 + v2.w*w31;
                    a30 += v3.x*w00 + v3.y*w10 + v3.z*w20 + v3.w*w30;
                    a31 += v3.x*w01 + v3.y*w11 + v3.z*w21 + v3.w*w31;
                }
                int   rows[4] = {r0, r1, r2, r3};
                float p0[4]   = {a00, a10, a20, a30};
                float p1[4]   = {a01, a11, a21, a31};
                #pragma unroll
                for (int r = 0; r < 4; r++) {
                    float sq  = wredsum(p0[r]*p0[r] + p1[r]*p1[r]);
                    float inv = 1.f / fmaxf(sqrtf(sq), 1e-6f);
                    float q0 = p0[r] * inv, q1 = p1[r] * inv;
                    if (iscp) {
                        cpt[l * Mn + rows[r]] = q0;
                        if (l < Dn - 32) cpt[(l + 32) * Mn + rows[r]] = q1;
                    } else {
                        tpn[rows[r] * DP + l]      = q0;
                        tpn[rows[r] * DP + l + 32] = q1;
                    }
                }
            } else {
                // cu pass: 13 m-rows x 1 e per lane, Wft streamed from L2
                int t  = p - 39;                 // 0..15
                int e0 = (t & 3) * 32 + l;       // e-group
                int m0 = (t >> 2) * 13; if (m0 > Mn - 13) m0 = Mn - 13;
                float acc[13];
                #pragma unroll
                for (int r = 0; r < 13; r++) acc[r] = 0.f;
                const float*  wp = g_Wft + e0;
                const float4* sb = (const float4*)(su + m0 * En);
                #pragma unroll 2
                for (int k4 = 0; k4 < 32; k4++) {
                    float w0 = wp[(4*k4+0) * En];
                    float w1 = wp[(4*k4+1) * En];
                    float w2 = wp[(4*k4+2) * En];
                    float w3 = wp[(4*k4+3) * En];
                    #pragma unroll
                    for (int r = 0; r < 13; r++) {
                        float4 s = sb[r * 32 + k4];
                        acc[r] += s.x*w0 + s.y*w1 + s.z*w2 + s.w*w3;
                    }
                }
                #pragma unroll
                for (int r = 0; r < 13; r++)
                    cu[(m0 + r) * En + e0] = acc[r];
            }
        }
        __syncthreads();

        // ========== phase 3: scores + softmax + epilogue, 4 j per warp-tile ==========
        float* wat = tv + w * 200;   // tv is dead; 4*50 floats per warp
        const float4* cuf = (const float4*)cu;
        for (int t = w; t < 26; t += NW) {
            int j0 = 4 * t;
            int jj0 = min(j0, Jn-1), jj1 = min(j0+1, Jn-1);
            int jj2 = min(j0+2, Jn-1), jj3 = min(j0+3, Jn-1);
            const bool act = (l < 25);
            const int m0 = act ? l : 0;
            const int m1 = m0 + 25;

            float s00=0,s01=0,s10=0,s11=0,s20=0,s21=0,s30=0,s31=0;
            const float4* t0p = (const float4*)(tpn + jj0 * DP);
            const float4* t1p = (const float4*)(tpn + jj1 * DP);
            const float4* t2p = (const float4*)(tpn + jj2 * DP);
            const float4* t3p = (const float4*)(tpn + jj3 * DP);
            #pragma unroll 3
            for (int d4 = 0; d4 < 15; d4++) {
                float4 t0 = t0p[d4], t1 = t1p[d4], t2 = t2p[d4], t3 = t3p[d4];
                const float* cp0 = cpt + d4 * 4 * Mn + m0;
                const float* cp1 = cpt + d4 * 4 * Mn + m1;
                #define SCORE_STEP(comp, off) { \
                    float c0 = cp0[(off) * Mn], c1 = cp1[(off) * Mn]; \
                    s00 += t0.comp * c0; s01 += t0.comp * c1; \
                    s10 += t1.comp * c0; s11 += t1.comp * c1; \
                    s20 += t2.comp * c0; s21 += t2.comp * c1; \
                    s30 += t3.comp * c0; s31 += t3.comp * c1; }
                SCORE_STEP(x, 0) SCORE_STEP(y, 1) SCORE_STEP(z, 2) SCORE_STEP(w, 3)
                #undef SCORE_STEP
            }
            float mk0 = act ? mskf[m0] : -INFINITY;
            float mk1 = act ? mskf[m1] : -INFINITY;
            float sr0[4] = {s00 + mk0, s10 + mk0, s20 + mk0, s30 + mk0};
            float sr1[4] = {s01 + mk1, s11 + mk1, s21 + mk1, s31 + mk1};
            #pragma unroll
            for (int r = 0; r < 4; r++) {
                float mx = wredmax(fmaxf(sr0[r], sr1[r]));
                float e0 = __expf(sr0[r] - mx);
                float e1 = __expf(sr1[r] - mx);
                float ss = wredsum(e0 + e1);
                float inv = 1.f / ss;
                if (act) {
                    wat[r * Mn + m0] = e0 * inv;
                    wat[r * Mn + m1] = e1 * inv;
                }
            }
            __syncwarp();

            float4 bq = ((const float4*)bfv)[l];
            float4 o0 = bq, o1 = bq, o2 = bq, o3 = bq;
            #pragma unroll 5
            for (int m = 0; m < Mn; m++) {
                float4 c = cuf[m * 32 + l];
                float a0 = wat[m], a1 = wat[Mn + m], a2 = wat[2*Mn + m], a3 = wat[3*Mn + m];
                o0.x += a0*c.x; o0.y += a0*c.y; o0.z += a0*c.z; o0.w += a0*c.w;
                o1.x += a1*c.x; o1.y += a1*c.y; o1.z += a1*c.z; o1.w += a1*c.w;
                o2.x += a2*c.x; o2.y += a2*c.y; o2.z += a2*c.z; o2.w += a2*c.w;
                o3.x += a3*c.x; o3.y += a3*c.y; o3.z += a3*c.z; o3.w += a3*c.w;
            }
            float4* op = (float4*)(out + (size_t)b * Jn * En);
            op[jj0 * 32 + l] = o0;
            op[jj1 * 32 + l] = o1;
            op[jj2 * 32 + l] = o2;
            op[jj3 * 32 + l] = o3;
            __syncwarp();   // wat reuse next tile
        }
    }
}

// ---------------- launch ----------------
extern "C" void kernel_launch(void* const* d_in, const int* in_sizes, int n_in,
                              void* d_out, int out_size)
{
    const int*   titems = (const int*)d_in[0];
    const int*   citems = (const int*)d_in[1];
    const int*   pad    = (const int*)d_in[2];
    const float* t_emb  = (const float*)d_in[3];
    const float* c_emb  = (const float*)d_in[4];
    const float* Ac_w   = (const float*)d_in[5];
    const float* Ac_b   = (const float*)d_in[6];
    const float* At_w   = (const float*)d_in[7];
    const float* At_b   = (const float*)d_in[8];
    const float* Bc_w   = (const float*)d_in[9];
    const float* Bc_b   = (const float*)d_in[10];
    const float* R_w    = (const float*)d_in[11];
    const float* R_b    = (const float*)d_in[12];
    float* out = (float*)d_out;

    cudaFuncSetAttribute(k_main, cudaFuncAttributeMaxDynamicSharedMemorySize, SMEM_BYTES);

    k_prep<<<En, En>>>(Bc_w, Bc_b, R_w, R_b);
    k_mask_init<<<(Bn * Mn + 255) / 256, 256>>>();
    k_mask_scatter<<<(Pn + 255) / 256, 256>>>(pad);
    k_main<<<GRID, TPB, SMEM_BYTES>>>(titems, citems, t_emb, c_emb,
                                      Ac_w, Ac_b, At_w, At_b, out);
}

// round 6
// speedup vs baseline: 1.0220x; 1.0220x over previous
#include <cuda_runtime.h>
#include <math.h>

#define Bn 512
#define Jn 101
#define Mn 50
#define En 128
#define Dn 60
#define DP 64
#define WS 65
#define Pn 5120
#define TPB 768
#define NW  (TPB/32)
#define GRID 148

// ---------------- device scratch ----------------
__device__ float g_Wft[En * En];   // Wft[k*128+e] = (R_w @ Bc_w)[e][k]
__device__ float g_bf[En];         // R_w @ Bc_b + R_b
__device__ float g_mask[Bn * Mn];  // 0 or -inf

__global__ void k_prep(const float* __restrict__ Bc_w, const float* __restrict__ Bc_b,
                       const float* __restrict__ R_w, const float* __restrict__ R_b)
{
    int e = blockIdx.x;
    int k = threadIdx.x;
    float acc = 0.f;
    for (int j = 0; j < En; j++)
        acc += R_w[e * En + j] * Bc_w[j * En + k];
    g_Wft[k * En + e] = acc;
    if (k == 0) {
        float s = R_b[e];
        for (int j = 0; j < En; j++) s += R_w[e * En + j] * Bc_b[j];
        g_bf[e] = s;
    }
}

__global__ void k_mask_init()
{
    int i = blockIdx.x * blockDim.x + threadIdx.x;
    if (i < Bn * Mn) g_mask[i] = 0.f;
}

__global__ void k_mask_scatter(const int* __restrict__ pad)
{
    int i = blockIdx.x * blockDim.x + threadIdx.x;
    if (i < Pn) {
        int b = pad[i];
        int m = pad[Pn + i];
        if (b >= 0 && b < Bn && m >= 0 && m < Mn)
            g_mask[b * Mn + m] = -INFINITY;
    }
}

// ---------------- smem layout (float offsets) ----------------
#define OFF_TV   0          // 101*128 = 12928 (overlaid by per-warp attn scratch in phase 3)
#define OFF_SU   12928      // 6400
#define OFF_TPN  19328      // 101*64 = 6464
#define OFF_CU   25792      // 6400
#define OFF_BFV  32192      // 128
#define OFF_ATW  32320      // 128*65 = 8320
#define OFF_ACW  40640      // 8320
#define OFF_CPT  48960      // 60*50 = 3000
#define OFF_ATB  51960      // 64
#define OFF_ACB  52024      // 64
#define OFF_MSK  52088      // 64
#define OFF_IDS  52152      // ints: cids 50 + jids 101
#define SMEM_FLOATS (OFF_IDS + 152)
#define SMEM_BYTES  (SMEM_FLOATS * 4)

__device__ __forceinline__ float wredsum(float v) {
    #pragma unroll
    for (int o = 16; o > 0; o >>= 1) v += __shfl_xor_sync(0xffffffffu, v, o);
    return v;
}
__device__ __forceinline__ float wredmax(float v) {
    #pragma unroll
    for (int o = 16; o > 0; o >>= 1) v = fmaxf(v, __shfl_xor_sync(0xffffffffu, v, o));
    return v;
}

__global__ __launch_bounds__(TPB, 1) void k_main(
    const int* __restrict__ titems, const int* __restrict__ citems,
    const float* __restrict__ t_emb, const float* __restrict__ c_emb,
    const float* __restrict__ Ac_w, const float* __restrict__ Ac_b,
    const float* __restrict__ At_w, const float* __restrict__ At_b,
    float* __restrict__ out)
{
    extern __shared__ float sm[];
    float* tv   = sm + OFF_TV;
    float* su   = sm + OFF_SU;
    float* tpn  = sm + OFF_TPN;
    float* cu   = sm + OFF_CU;
    float* bfv  = sm + OFF_BFV;
    float* atw  = sm + OFF_ATW;
    float* acw  = sm + OFF_ACW;
    float* cpt  = sm + OFF_CPT;
    float* atb  = sm + OFF_ATB;
    float* acb  = sm + OFF_ACB;
    float* mskf = sm + OFF_MSK;
    int*   cids = (int*)(sm + OFF_IDS);
    int*   jids = cids + Mn;

    const int tid = threadIdx.x;
    const int w   = tid >> 5, l = tid & 31;

    // ======== stage weights ONCE per CTA ========
    if (tid < DP) {
        atb[tid] = (tid < Dn) ? At_b[tid] : 0.f;
        acb[tid] = (tid < Dn) ? Ac_b[tid] : 0.f;
    }
    if (tid < En) bfv[tid] = g_bf[tid];
    for (int i = tid; i < Dn * En; i += TPB) {
        int d = i >> 7, k = i & 127;
        atw[k * WS + d] = At_w[i];
        acw[k * WS + d] = Ac_w[i];
    }
    for (int i = tid; i < En * 4; i += TPB) {
        int k = i >> 2, c = Dn + (i & 3);
        atw[k * WS + c] = 0.f;
        acw[k * WS + c] = 0.f;
    }

    // ======== persistent batch loop ========
    for (int b = blockIdx.x; b < Bn; b += GRID) {
        __syncthreads();   // weights ready / previous batch phase-3 done

        if (tid < Mn) { cids[tid] = citems[b * Mn + tid]; mskf[tid] = g_mask[b * Mn + tid]; }
        if (tid < Jn) jids[tid] = titems[b * Jn + tid];
        __syncthreads();

        // gather embeddings (float4)
        {
            const float4* cef = (const float4*)c_emb;
            const float4* tef = (const float4*)t_emb;
            float4* suf = (float4*)su;
            float4* tvf = (float4*)tv;
            for (int i = tid; i < Mn * 32; i += TPB)
                suf[i] = cef[(size_t)cids[i >> 5] * 32 + (i & 31)];
            for (int i = tid; i < Jn * 32; i += TPB)
                tvf[i] = tef[(size_t)jids[i >> 5] * 32 + (i & 31)];
        }
        __syncthreads();

        // ========== phase 2: 47 warp-passes (13 cp + 26 tp + 8 cu) ==========
        for (int p = w; p < 47; p += NW) {
            if (p < 39) {
                // projection pass: 4 rows x (d0=l, d1=l+32), normalized on store
                const bool iscp = (p < 13);
                const int base = iscp ? 4 * p : 4 * (p - 13);
                const int rmax = iscp ? (Mn - 1) : (Jn - 1);
                const float* src  = iscp ? su : tv;
                const float* wkd  = iscp ? acw : atw;
                const float* bias = iscp ? acb : atb;
                int r0 = min(base,     rmax), r1 = min(base + 1, rmax);
                int r2 = min(base + 2, rmax), r3 = min(base + 3, rmax);
                const float4* s0 = (const float4*)(src + r0 * En);
                const float4* s1 = (const float4*)(src + r1 * En);
                const float4* s2 = (const float4*)(src + r2 * En);
                const float4* s3 = (const float4*)(src + r3 * En);
                float bl0 = bias[l], bl1 = bias[l + 32];
                float a00 = bl0, a01 = bl1, a10 = bl0, a11 = bl1;
                float a20 = bl0, a21 = bl1, a30 = bl0, a31 = bl1;
                #pragma unroll 4
                for (int k4 = 0; k4 < 32; k4++) {
                    float4 v0 = s0[k4], v1 = s1[k4], v2 = s2[k4], v3 = s3[k4];
                    const float* wr = wkd + k4 * 4 * WS;
                    float w00 = wr[l],        w01 = wr[l + 32];
                    float w10 = wr[WS + l],   w11 = wr[WS + l + 32];
                    float w20 = wr[2*WS + l], w21 = wr[2*WS + l + 32];
                    float w30 = wr[3*WS + l], w31 = wr[3*WS + l + 32];
                    a00 += v0.x*w00 + v0.y*w10 + v0.z*w20 + v0.w*w30;
                    a01 += v0.x*w01 + v0.y*w11 + v0.z*w21 + v0.w*w31;
                    a10 += v1.x*w00 + v1.y*w10 + v1.z*w20 + v1.w*w30;
                    a11 += v1.x*w01 + v1.y*w11 + v1.z*w21 + v1.w*w31;
                    a20 += v2.x*w00 + v2.y*w10 + v2.z*w20 + v2.w*w30;
                    a21 += v2.x*w01 + v2.y*w11 + v2.z*w21 + v2.w*w31;
                    a30 += v3.x*w00 + v3.y*w10 + v3.z*w20 + v3.w*w30;
                    a31 += v3.x*w01 + v3.y*w11 + v3.z*w21 + v3.w*w31;
                }
                int   rows[4] = {r0, r1, r2, r3};
                float p0[4]   = {a00, a10, a20, a30};
                float p1[4]   = {a01, a11, a21, a31};
                #pragma unroll
                for (int r = 0; r < 4; r++) {
                    float sq  = wredsum(p0[r]*p0[r] + p1[r]*p1[r]);
                    float inv = 1.f / fmaxf(sqrtf(sq), 1e-6f);
                    float q0 = p0[r] * inv, q1 = p1[r] * inv;
                    if (iscp) {
                        cpt[l * Mn + rows[r]] = q0;
                        if (l < Dn - 32) cpt[(l + 32) * Mn + rows[r]] = q1;
                    } else {
                        tpn[rows[r] * DP + l]      = q0;
                        tpn[rows[r] * DP + l + 32] = q1;
                    }
                }
            } else {
                // cu pass: 13 m-rows x 2 e per lane, Wft streamed from L2
                int t  = p - 39;                 // 0..7
                int g  = t & 1, q = t >> 1;      // e-half, m-quarter
                int e0 = g * 32 + l;             // second e is e0+64
                int m0 = q * 13; if (m0 > Mn - 13) m0 = Mn - 13;
                float accA[13], accB[13];
                #pragma unroll
                for (int r = 0; r < 13; r++) { accA[r] = 0.f; accB[r] = 0.f; }
                const float*  wp0 = g_Wft + e0;
                const float*  wp1 = g_Wft + e0 + 64;
                const float4* sb  = (const float4*)(su + m0 * En);
                #pragma unroll 2
                for (int k4 = 0; k4 < 32; k4++) {
                    float wA0 = wp0[(4*k4+0) * En], wB0 = wp1[(4*k4+0) * En];
                    float wA1 = wp0[(4*k4+1) * En], wB1 = wp1[(4*k4+1) * En];
                    float wA2 = wp0[(4*k4+2) * En], wB2 = wp1[(4*k4+2) * En];
                    float wA3 = wp0[(4*k4+3) * En], wB3 = wp1[(4*k4+3) * En];
                    #pragma unroll
                    for (int r = 0; r < 13; r++) {
                        float4 s = sb[r * 32 + k4];
                        accA[r] += s.x*wA0 + s.y*wA1 + s.z*wA2 + s.w*wA3;
                        accB[r] += s.x*wB0 + s.y*wB1 + s.z*wB2 + s.w*wB3;
                    }
                }
                #pragma unroll
                for (int r = 0; r < 13; r++) {
                    cu[(m0 + r) * En + e0]      = accA[r];
                    cu[(m0 + r) * En + e0 + 64] = accB[r];
                }
            }
        }
        __syncthreads();

        // ========== phase 3: scores + softmax + epilogue, 5 j per warp-tile (21 tiles) ==========
        float* wat = tv + w * 256;   // tv is dead; 5*50=250 floats per warp
        const float4* cuf = (const float4*)cu;
        for (int t = w; t < 21; t += NW) {
            int j0 = 5 * t;
            int jj[5];
            const float4* tp_[5];
            #pragma unroll
            for (int i = 0; i < 5; i++) {
                jj[i] = min(j0 + i, Jn - 1);
                tp_[i] = (const float4*)(tpn + jj[i] * DP);
            }
            const bool act = (l < 25);
            const int m0 = act ? l : 0;
            const int m1 = m0 + 25;

            float s0[5], s1[5];
            #pragma unroll
            for (int i = 0; i < 5; i++) { s0[i] = 0.f; s1[i] = 0.f; }
            #pragma unroll 3
            for (int d4 = 0; d4 < 15; d4++) {
                float4 tt[5];
                #pragma unroll
                for (int i = 0; i < 5; i++) tt[i] = tp_[i][d4];
                const float* cp0 = cpt + d4 * 4 * Mn + m0;
                const float* cp1 = cpt + d4 * 4 * Mn + m1;
                #define SCORE_STEP(comp, off) { \
                    float c0 = cp0[(off) * Mn], c1 = cp1[(off) * Mn]; \
                    _Pragma("unroll") \
                    for (int i = 0; i < 5; i++) { \
                        s0[i] += tt[i].comp * c0; s1[i] += tt[i].comp * c1; } }
                SCORE_STEP(x, 0) SCORE_STEP(y, 1) SCORE_STEP(z, 2) SCORE_STEP(w, 3)
                #undef SCORE_STEP
            }
            float mk0 = act ? mskf[m0] : -INFINITY;
            float mk1 = act ? mskf[m1] : -INFINITY;
            #pragma unroll
            for (int i = 0; i < 5; i++) {
                float v0 = s0[i] + mk0, v1 = s1[i] + mk1;
                float mx = wredmax(fmaxf(v0, v1));
                float e0 = __expf(v0 - mx);
                float e1 = __expf(v1 - mx);
                float ss = wredsum(e0 + e1);
                float inv = 1.f / ss;
                if (act) {
                    wat[i * Mn + m0] = e0 * inv;
                    wat[i * Mn + m1] = e1 * inv;
                }
            }
            __syncwarp();

            float4 bq = ((const float4*)bfv)[l];
            float4 o[5];
            #pragma unroll
            for (int i = 0; i < 5; i++) o[i] = bq;
            #pragma unroll 5
            for (int m = 0; m < Mn; m++) {
                float4 c = cuf[m * 32 + l];
                #pragma unroll
                for (int i = 0; i < 5; i++) {
                    float a = wat[i * Mn + m];
                    o[i].x += a*c.x; o[i].y += a*c.y; o[i].z += a*c.z; o[i].w += a*c.w;
                }
            }
            float4* op = (float4*)(out + (size_t)b * Jn * En);
            #pragma unroll
            for (int i = 0; i < 5; i++)
                op[jj[i] * 32 + l] = o[i];
            __syncwarp();   // wat reuse next tile
        }
    }
}

// ---------------- launch ----------------
extern "C" void kernel_launch(void* const* d_in, const int* in_sizes, int n_in,
                              void* d_out, int out_size)
{
    const int*   titems = (const int*)d_in[0];
    const int*   citems = (const int*)d_in[1];
    const int*   pad    = (const int*)d_in[2];
    const float* t_emb  = (const float*)d_in[3];
    const float* c_emb  = (const float*)d_in[4];
    const float* Ac_w   = (const float*)d_in[5];
    const float* Ac_b   = (const float*)d_in[6];
    const float* At_w   = (const float*)d_in[7];
    const float* At_b   = (const float*)d_in[8];
    const float* Bc_w   = (const float*)d_in[9];
    const float* Bc_b   = (const float*)d_in[10];
    const float* R_w    = (const float*)d_in[11];
    const float* R_b    = (const float*)d_in[12];
    float* out = (float*)d_out;

    cudaFuncSetAttribute(k_main, cudaFuncAttributeMaxDynamicSharedMemorySize, SMEM_BYTES);

    k_prep<<<En, En>>>(Bc_w, Bc_b, R_w, R_b);
    k_mask_init<<<(Bn * Mn + 255) / 256, 256>>>();
    k_mask_scatter<<<(Pn + 255) / 256, 256>>>(pad);
    k_main<<<GRID, TPB, SMEM_BYTES>>>(titems, citems, t_emb, c_emb,
                                      Ac_w, Ac_b, At_w, At_b, out);
}